// round 1
// baseline (speedup 1.0000x reference)
#include <cuda_runtime.h>
#include <math.h>

// Problem constants
#define BB 4
#define LL 2048
#define DD 1024
#define DIN 1024          // d_inner
#define NS 8              // d_state
#define RR 64             // dt_rank
#define DBLW (RR + 2*NS)  // 80

// ---------------- scratch (device globals; no allocation) ----------------
__device__ float g_xnorm[BB*LL*DD];        // 32 MB
__device__ float g_xz[BB*LL*2*DIN];        // 64 MB
__device__ float g_xconv[BB*LL*DIN];       // 32 MB
__device__ float g_dbl[BB*LL*DBLW];        // 2.5 MB
__device__ float g_dt[BB*LL*DIN];          // 32 MB
__device__ float g_y[BB*LL*DIN];           // 32 MB

// ---------------- RMSNorm ----------------
__global__ __launch_bounds__(256) void rmsnorm_kernel(const float* __restrict__ x,
                                                      const float* __restrict__ w) {
    const int row = blockIdx.x;               // B*L rows
    const float* xr = x + (size_t)row * DD;
    float v[4];
    float ss = 0.f;
#pragma unroll
    for (int i = 0; i < 4; i++) {
        v[i] = xr[threadIdx.x + i * 256];
        ss += v[i] * v[i];
    }
#pragma unroll
    for (int o = 16; o > 0; o >>= 1) ss += __shfl_xor_sync(0xffffffffu, ss, o);
    __shared__ float red[8];
    if ((threadIdx.x & 31) == 0) red[threadIdx.x >> 5] = ss;
    __syncthreads();
    float tot = 0.f;
#pragma unroll
    for (int i = 0; i < 8; i++) tot += red[i];
    const float sc = rsqrtf(tot * (1.f / DD) + 1e-5f);
    float* outr = g_xnorm + (size_t)row * DD;
#pragma unroll
    for (int i = 0; i < 4; i++) {
        const int d = threadIdx.x + i * 256;
        outr[d] = v[i] * sc * w[d];
    }
}

// ---------------- generic SGEMM: C[m,e] = sum_k A[m,k] * W[e,k] ----------------
// A: [M, K] row-major with row stride lda
// W: [E, K] row-major with row stride ldw
// epi == 1: v += bias[e]; v = softplus(v)
#define BM 128
#define BN 128
#define BKK 8

__global__ __launch_bounds__(256) void sgemm_kernel(
    const float* __restrict__ A, int lda,
    const float* __restrict__ W, int ldw,
    float* __restrict__ C, int ldc,
    int K, int E,
    const float* __restrict__ bias, int epi)
{
    __shared__ float As[BKK][BM + 4];
    __shared__ float Ws[BKK][BN + 4];

    const int tid = threadIdx.x;
    const int m0 = blockIdx.y * BM;
    const int e0 = blockIdx.x * BN;

    // load mapping: each thread loads one float4 of one row (128 rows x 8 k)
    const int lrow = tid >> 1;        // 0..127
    const int lk = (tid & 1) * 4;     // 0 or 4

    // compute mapping: 16x16 threads, each 8x8 output
    const int ty = tid >> 4;          // 0..15
    const int tx = tid & 15;          // 0..15

    float acc[8][8];
#pragma unroll
    for (int i = 0; i < 8; i++)
#pragma unroll
        for (int j = 0; j < 8; j++) acc[i][j] = 0.f;

    const float* aload = A + (size_t)(m0 + lrow) * lda + lk;
    const bool wvalid = (e0 + lrow) < E;
    const int wrow = wvalid ? (e0 + lrow) : (E - 1);
    const float* wload = W + (size_t)wrow * ldw + lk;

    for (int k0 = 0; k0 < K; k0 += BKK) {
        const float4 av = *(const float4*)(aload + k0);
        float4 wv = make_float4(0.f, 0.f, 0.f, 0.f);
        if (wvalid) wv = *(const float4*)(wload + k0);

        As[lk + 0][lrow] = av.x; As[lk + 1][lrow] = av.y;
        As[lk + 2][lrow] = av.z; As[lk + 3][lrow] = av.w;
        Ws[lk + 0][lrow] = wv.x; Ws[lk + 1][lrow] = wv.y;
        Ws[lk + 2][lrow] = wv.z; Ws[lk + 3][lrow] = wv.w;
        __syncthreads();

#pragma unroll
        for (int kk = 0; kk < BKK; kk++) {
            const float4 a0 = *(const float4*)&As[kk][ty * 8];
            const float4 a1 = *(const float4*)&As[kk][ty * 8 + 4];
            const float4 b0 = *(const float4*)&Ws[kk][tx * 8];
            const float4 b1 = *(const float4*)&Ws[kk][tx * 8 + 4];
            const float ar[8] = {a0.x, a0.y, a0.z, a0.w, a1.x, a1.y, a1.z, a1.w};
            const float br[8] = {b0.x, b0.y, b0.z, b0.w, b1.x, b1.y, b1.z, b1.w};
#pragma unroll
            for (int i = 0; i < 8; i++)
#pragma unroll
                for (int j = 0; j < 8; j++) acc[i][j] += ar[i] * br[j];
        }
        __syncthreads();
    }

#pragma unroll
    for (int i = 0; i < 8; i++) {
        const int m = m0 + ty * 8 + i;
#pragma unroll
        for (int j = 0; j < 8; j++) {
            const int e = e0 + tx * 8 + j;
            if (e < E) {
                float v = acc[i][j];
                if (epi == 1) {
                    v += bias[e];
                    // numerically stable softplus: max(v,0) + log1p(exp(-|v|))
                    v = fmaxf(v, 0.f) + log1pf(__expf(-fabsf(v)));
                }
                C[(size_t)m * ldc + e] = v;
            }
        }
    }
}

// ---------------- causal depthwise conv (K=4) + bias + silu ----------------
__global__ __launch_bounds__(256) void conv_silu_kernel(const float* __restrict__ conv_w,
                                                        const float* __restrict__ conv_b) {
    const int idx = blockIdx.x * blockDim.x + threadIdx.x;
    if (idx >= BB * LL * DIN) return;
    const int d = idx % DIN;
    const int l = (idx / DIN) % LL;
    const int b = idx / (DIN * LL);
    const float* w = conv_w + d * 4;
    float acc = conv_b[d];
#pragma unroll
    for (int j = 0; j < 4; j++) {
        const int ls = l - 3 + j;
        if (ls >= 0) {
            acc += w[j] * g_xz[((size_t)(b * LL + ls)) * (2 * DIN) + d];
        }
    }
    g_xconv[idx] = acc / (1.f + __expf(-acc));   // silu
}

// ---------------- selective scan + D skip + silu(z) gating ----------------
__global__ __launch_bounds__(128) void scan_kernel(const float* __restrict__ A_log,
                                                   const float* __restrict__ D_skip) {
    const int b = blockIdx.y;
    const int d = blockIdx.x * blockDim.x + threadIdx.x;
    const int tid = threadIdx.x;

    float A[NS];
#pragma unroll
    for (int n = 0; n < NS; n++) A[n] = -__expf(A_log[d * NS + n]);
    const float dsk = D_skip[d];

    float h[NS];
#pragma unroll
    for (int n = 0; n < NS; n++) h[n] = 0.f;

    __shared__ float sB[64][NS];
    __shared__ float sC[64][NS];

    for (int l0 = 0; l0 < LL; l0 += 64) {
        // cooperative stage of B/C for 64 timesteps (16 floats per step)
        for (int i = tid; i < 64 * 16; i += 128) {
            const int ll = i >> 4;
            const int c = i & 15;
            const float v = g_dbl[((size_t)(b * LL + l0 + ll)) * DBLW + RR + c];
            if (c < NS) sB[ll][c] = v;
            else        sC[ll][c - NS] = v;
        }
        __syncthreads();

        for (int j = 0; j < 64; j++) {
            const int l = l0 + j;
            const size_t idx = ((size_t)(b * LL + l)) * DIN + d;
            const float dtv = g_dt[idx];
            const float xv = g_xconv[idx];
            const float dtx = dtv * xv;
            float yv = 0.f;
#pragma unroll
            for (int n = 0; n < NS; n++) {
                const float da = __expf(dtv * A[n]);
                h[n] = da * h[n] + dtx * sB[j][n];
                yv += h[n] * sC[j][n];
            }
            const float z = g_xz[((size_t)(b * LL + l)) * (2 * DIN) + DIN + d];
            const float sz = z / (1.f + __expf(-z));
            g_y[idx] = (yv + dsk * xv) * sz;
        }
        __syncthreads();
    }
}

// ---------------- launch ----------------
extern "C" void kernel_launch(void* const* d_in, const int* in_sizes, int n_in,
                              void* d_out, int out_size) {
    const float* hidden = (const float*)d_in[0];
    const float* norm_w = (const float*)d_in[1];
    const float* in_proj_w = (const float*)d_in[2];
    const float* conv_w = (const float*)d_in[3];
    const float* conv_b = (const float*)d_in[4];
    const float* x_proj_w = (const float*)d_in[5];
    const float* dt_proj_w = (const float*)d_in[6];
    const float* dt_proj_b = (const float*)d_in[7];
    const float* A_log = (const float*)d_in[8];
    const float* D_skip = (const float*)d_in[9];
    const float* out_proj_w = (const float*)d_in[10];
    float* out = (float*)d_out;

    float *p_xnorm, *p_xz, *p_xconv, *p_dbl, *p_dt, *p_y;
    cudaGetSymbolAddress((void**)&p_xnorm, g_xnorm);
    cudaGetSymbolAddress((void**)&p_xz, g_xz);
    cudaGetSymbolAddress((void**)&p_xconv, g_xconv);
    cudaGetSymbolAddress((void**)&p_dbl, g_dbl);
    cudaGetSymbolAddress((void**)&p_dt, g_dt);
    cudaGetSymbolAddress((void**)&p_y, g_y);

    const int M = BB * LL;  // 8192

    // 1. RMSNorm
    rmsnorm_kernel<<<M, 256>>>(hidden, norm_w);

    // 2. in_proj: xz[M, 2*DIN] = xnorm[M, DD] @ in_proj_w[2*DIN, DD]^T
    {
        dim3 grid((2 * DIN + BN - 1) / BN, M / BM);
        sgemm_kernel<<<grid, 256>>>(p_xnorm, DD, in_proj_w, DD,
                                    p_xz, 2 * DIN, DD, 2 * DIN, nullptr, 0);
    }

    // 3. causal depthwise conv + silu
    {
        const int total = BB * LL * DIN;
        conv_silu_kernel<<<(total + 255) / 256, 256>>>(conv_w, conv_b);
    }

    // 4. x_proj: dbl[M, 80] = xconv[M, DIN] @ x_proj_w[80, DIN]^T
    {
        dim3 grid((DBLW + BN - 1) / BN, M / BM);
        sgemm_kernel<<<grid, 256>>>(p_xconv, DIN, x_proj_w, DIN,
                                    p_dbl, DBLW, DIN, DBLW, nullptr, 0);
    }

    // 5. dt_proj + bias + softplus: dt[M, DIN] = softplus(dbl[:, :64] @ dt_proj_w[DIN,64]^T + b)
    {
        dim3 grid((DIN + BN - 1) / BN, M / BM);
        sgemm_kernel<<<grid, 256>>>(p_dbl, DBLW, dt_proj_w, RR,
                                    p_dt, DIN, RR, DIN, dt_proj_b, 1);
    }

    // 6. selective scan + gating
    {
        dim3 grid(DIN / 128, BB);
        scan_kernel<<<grid, 128>>>(A_log, D_skip);
    }

    // 7. out_proj: out[M, DD] = y[M, DIN] @ out_proj_w[DD, DIN]^T
    {
        dim3 grid((DD + BN - 1) / BN, M / BM);
        sgemm_kernel<<<grid, 256>>>(p_y, DIN, out_proj_w, DIN,
                                    out, DD, DIN, DD, nullptr, 0);
    }
}

// round 2
// speedup vs baseline: 3.2457x; 3.2457x over previous
#include <cuda_runtime.h>
#include <math.h>
#include <stdint.h>

// Problem constants
#define BB 4
#define LL 2048
#define DD 1024
#define DIN 1024          // d_inner
#define NS 8              // d_state
#define RR 64             // dt_rank
#define DBLW (RR + 2*NS)  // 80
#define SEG 16            // scan segments
#define SEGL (LL / SEG)   // 128

// ---------------- scratch (device globals; no allocation) ----------------
__device__ float g_xnorm[BB*LL*DD];
__device__ float g_xz[BB*LL*2*DIN];
__device__ float g_xconv[BB*LL*DIN];
__device__ float g_dbl[BB*LL*DBLW];
__device__ float g_dt[BB*LL*DIN];
__device__ float g_y[BB*LL*DIN];
__device__ float g_segA[BB*SEG*NS*DIN];
__device__ float g_segB[BB*SEG*NS*DIN];
__device__ float g_hin[BB*SEG*NS*DIN];

// ---------------- helpers ----------------
__device__ __forceinline__ uint32_t f2tf32(float f) {
    uint32_t u;
    asm("cvt.rna.tf32.f32 %0, %1;" : "=r"(u) : "f"(f));
    return u;
}

__device__ __forceinline__ void mma_tf32(float c[4], const uint32_t a[4], const uint32_t b[2]) {
    asm volatile(
        "mma.sync.aligned.m16n8k8.row.col.f32.tf32.tf32.f32 "
        "{%0,%1,%2,%3}, {%4,%5,%6,%7}, {%8,%9}, {%0,%1,%2,%3};"
        : "+f"(c[0]), "+f"(c[1]), "+f"(c[2]), "+f"(c[3])
        : "r"(a[0]), "r"(a[1]), "r"(a[2]), "r"(a[3]), "r"(b[0]), "r"(b[1]));
}

// ---------------- RMSNorm ----------------
__global__ __launch_bounds__(256) void rmsnorm_kernel(const float* __restrict__ x,
                                                      const float* __restrict__ w) {
    const int row = blockIdx.x;
    const float* xr = x + (size_t)row * DD;
    float v[4];
    float ss = 0.f;
#pragma unroll
    for (int i = 0; i < 4; i++) {
        v[i] = xr[threadIdx.x + i * 256];
        ss += v[i] * v[i];
    }
#pragma unroll
    for (int o = 16; o > 0; o >>= 1) ss += __shfl_xor_sync(0xffffffffu, ss, o);
    __shared__ float red[8];
    if ((threadIdx.x & 31) == 0) red[threadIdx.x >> 5] = ss;
    __syncthreads();
    float tot = 0.f;
#pragma unroll
    for (int i = 0; i < 8; i++) tot += red[i];
    const float sc = rsqrtf(tot * (1.f / DD) + 1e-5f);
    float* outr = g_xnorm + (size_t)row * DD;
#pragma unroll
    for (int i = 0; i < 4; i++) {
        const int d = threadIdx.x + i * 256;
        outr[d] = v[i] * sc * w[d];
    }
}

// ---------------- TF32 tensor-core GEMM ----------------
// C[m,e] = sum_k A[m,k] * W[e,k]   (A: [M,K] lda, W: [E,K] ldw, C: [M,?] ldc)
// BM=BN=128, BK=16, 256 threads (8 warps, 4x2 warp grid, 32x64 per warp)
// epi==1: v = softplus(v + bias[e])
__global__ __launch_bounds__(256, 2) void gemm_tf32(
    const float* __restrict__ A, int lda,
    const float* __restrict__ W, int ldw,
    float* __restrict__ C, int ldc,
    int K, int E,
    const float* __restrict__ bias, int epi)
{
    __shared__ uint32_t As[2][16][132];
    __shared__ uint32_t Bs[2][16][132];

    const int tid = threadIdx.x;
    const int lane = tid & 31;
    const int wid = tid >> 5;
    const int m0 = blockIdx.y * 128;
    const int e0 = blockIdx.x * 128;
    const int mw = (wid & 3) * 32;
    const int nw = (wid >> 2) * 64;

    // producer mapping: each thread loads 2 float4 per matrix per k-tile
    const int am = tid >> 2;            // 0..63 (and +64)
    const int kq = (tid & 3) * 4;       // 0,4,8,12

    const float* aP0 = A + (size_t)(m0 + am) * lda + kq;
    const float* aP1 = A + (size_t)(m0 + am + 64) * lda + kq;
    const int er0 = e0 + am, er1 = e0 + am + 64;
    const bool v0 = er0 < E, v1 = er1 < E;
    const float* wP0 = W + (size_t)(v0 ? er0 : 0) * ldw + kq;
    const float* wP1 = W + (size_t)(v1 ? er1 : 0) * ldw + kq;

    float acc[2][8][4];
#pragma unroll
    for (int i = 0; i < 2; i++)
#pragma unroll
        for (int j = 0; j < 8; j++)
#pragma unroll
            for (int l = 0; l < 4; l++) acc[i][j][l] = 0.f;

    const int T = K / 16;
    float4 ra0, ra1, rw0, rw1;
    const float4 z4 = make_float4(0.f, 0.f, 0.f, 0.f);

    // preload tile 0
    ra0 = *(const float4*)aP0;
    ra1 = *(const float4*)aP1;
    rw0 = v0 ? *(const float4*)wP0 : z4;
    rw1 = v1 ? *(const float4*)wP1 : z4;
    {
        As[0][kq + 0][am] = f2tf32(ra0.x); As[0][kq + 1][am] = f2tf32(ra0.y);
        As[0][kq + 2][am] = f2tf32(ra0.z); As[0][kq + 3][am] = f2tf32(ra0.w);
        As[0][kq + 0][am + 64] = f2tf32(ra1.x); As[0][kq + 1][am + 64] = f2tf32(ra1.y);
        As[0][kq + 2][am + 64] = f2tf32(ra1.z); As[0][kq + 3][am + 64] = f2tf32(ra1.w);
        Bs[0][kq + 0][am] = f2tf32(rw0.x); Bs[0][kq + 1][am] = f2tf32(rw0.y);
        Bs[0][kq + 2][am] = f2tf32(rw0.z); Bs[0][kq + 3][am] = f2tf32(rw0.w);
        Bs[0][kq + 0][am + 64] = f2tf32(rw1.x); Bs[0][kq + 1][am + 64] = f2tf32(rw1.y);
        Bs[0][kq + 2][am + 64] = f2tf32(rw1.z); Bs[0][kq + 3][am + 64] = f2tf32(rw1.w);
    }
    __syncthreads();

    const int g = lane >> 2;
    const int tg = lane & 3;

    for (int t = 0; t < T; t++) {
        const int buf = t & 1;
        if (t + 1 < T) {
            const int ko = (t + 1) * 16;
            ra0 = *(const float4*)(aP0 + ko);
            ra1 = *(const float4*)(aP1 + ko);
            rw0 = v0 ? *(const float4*)(wP0 + ko) : z4;
            rw1 = v1 ? *(const float4*)(wP1 + ko) : z4;
        }

#pragma unroll
        for (int ks = 0; ks < 2; ks++) {
            const int kk = ks * 8;
            uint32_t af[2][4];
            uint32_t bf[8][2];
#pragma unroll
            for (int mt = 0; mt < 2; mt++) {
                const int mb = mw + mt * 16 + g;
                af[mt][0] = As[buf][kk + tg][mb];
                af[mt][1] = As[buf][kk + tg][mb + 8];
                af[mt][2] = As[buf][kk + 4 + tg][mb];
                af[mt][3] = As[buf][kk + 4 + tg][mb + 8];
            }
#pragma unroll
            for (int nt = 0; nt < 8; nt++) {
                const int nb = nw + nt * 8 + g;
                bf[nt][0] = Bs[buf][kk + tg][nb];
                bf[nt][1] = Bs[buf][kk + 4 + tg][nb];
            }
#pragma unroll
            for (int mt = 0; mt < 2; mt++)
#pragma unroll
                for (int nt = 0; nt < 8; nt++)
                    mma_tf32(acc[mt][nt], af[mt], bf[nt]);
        }

        if (t + 1 < T) {
            const int nb = buf ^ 1;
            As[nb][kq + 0][am] = f2tf32(ra0.x); As[nb][kq + 1][am] = f2tf32(ra0.y);
            As[nb][kq + 2][am] = f2tf32(ra0.z); As[nb][kq + 3][am] = f2tf32(ra0.w);
            As[nb][kq + 0][am + 64] = f2tf32(ra1.x); As[nb][kq + 1][am + 64] = f2tf32(ra1.y);
            As[nb][kq + 2][am + 64] = f2tf32(ra1.z); As[nb][kq + 3][am + 64] = f2tf32(ra1.w);
            Bs[nb][kq + 0][am] = f2tf32(rw0.x); Bs[nb][kq + 1][am] = f2tf32(rw0.y);
            Bs[nb][kq + 2][am] = f2tf32(rw0.z); Bs[nb][kq + 3][am] = f2tf32(rw0.w);
            Bs[nb][kq + 0][am + 64] = f2tf32(rw1.x); Bs[nb][kq + 1][am + 64] = f2tf32(rw1.y);
            Bs[nb][kq + 2][am + 64] = f2tf32(rw1.z); Bs[nb][kq + 3][am + 64] = f2tf32(rw1.w);
        }
        __syncthreads();
    }

    // epilogue
#pragma unroll
    for (int mt = 0; mt < 2; mt++) {
        const int r0 = m0 + mw + mt * 16 + g;
        const int r1 = r0 + 8;
#pragma unroll
        for (int nt = 0; nt < 8; nt++) {
            const int c0 = e0 + nw + nt * 8 + tg * 2;
#pragma unroll
            for (int jj = 0; jj < 2; jj++) {
                const int c = c0 + jj;
                if (c < E) {
                    float va = acc[mt][nt][jj];
                    float vb = acc[mt][nt][2 + jj];
                    if (epi == 1) {
                        const float bv = bias[c];
                        va += bv;
                        va = fmaxf(va, 0.f) + log1pf(__expf(-fabsf(va)));
                        vb += bv;
                        vb = fmaxf(vb, 0.f) + log1pf(__expf(-fabsf(vb)));
                    }
                    C[(size_t)r0 * ldc + c] = va;
                    C[(size_t)r1 * ldc + c] = vb;
                }
            }
        }
    }
}

// ---------------- causal depthwise conv (K=4) + bias + silu ----------------
__global__ __launch_bounds__(256) void conv_silu_kernel(const float* __restrict__ conv_w,
                                                        const float* __restrict__ conv_b) {
    const int idx = blockIdx.x * blockDim.x + threadIdx.x;
    if (idx >= BB * LL * DIN) return;
    const int d = idx % DIN;
    const int l = (idx / DIN) % LL;
    const int b = idx / (DIN * LL);
    const float* w = conv_w + d * 4;
    float acc = conv_b[d];
#pragma unroll
    for (int j = 0; j < 4; j++) {
        const int ls = l - 3 + j;
        if (ls >= 0) {
            acc += w[j] * g_xz[((size_t)(b * LL + ls)) * (2 * DIN) + d];
        }
    }
    g_xconv[idx] = acc / (1.f + __expf(-acc));
}

// ---------------- chunked selective scan ----------------
// pass1: per (b, seg, d): cumprod(dA) and local h (h_in = 0)
__global__ __launch_bounds__(128) void scan_pass1(const float* __restrict__ A_log) {
    const int b = blockIdx.z;
    const int s = blockIdx.y;
    const int d = blockIdx.x * 128 + threadIdx.x;
    const int tid = threadIdx.x;
    const int l0 = s * SEGL;

    float A[NS];
#pragma unroll
    for (int n = 0; n < NS; n++) A[n] = -__expf(A_log[d * NS + n]);

    float p[NS], h[NS];
#pragma unroll
    for (int n = 0; n < NS; n++) { p[n] = 1.f; h[n] = 0.f; }

    __shared__ float sB[SEGL][NS];
    for (int i = tid; i < SEGL * NS; i += 128) {
        const int ll = i >> 3;
        const int n = i & 7;
        sB[ll][n] = g_dbl[((size_t)(b * LL + l0 + ll)) * DBLW + RR + n];
    }
    __syncthreads();

    for (int j = 0; j < SEGL; j++) {
        const size_t idx = ((size_t)(b * LL + l0 + j)) * DIN + d;
        const float dtv = g_dt[idx];
        const float xv = g_xconv[idx];
        const float dtx = dtv * xv;
#pragma unroll
        for (int n = 0; n < NS; n++) {
            const float da = __expf(dtv * A[n]);
            p[n] *= da;
            h[n] = da * h[n] + dtx * sB[j][n];
        }
    }

#pragma unroll
    for (int n = 0; n < NS; n++) {
        const size_t o = ((size_t)((b * SEG + s) * NS + n)) * DIN + d;
        g_segA[o] = p[n];
        g_segB[o] = h[n];
    }
}

// pass2: sequential combine across segments (tiny)
__global__ __launch_bounds__(256) void scan_pass2() {
    const int gidx = blockIdx.x * 256 + threadIdx.x;
    if (gidx >= BB * DIN) return;
    const int b = gidx / DIN;
    const int d = gidx % DIN;
    float h[NS];
#pragma unroll
    for (int n = 0; n < NS; n++) h[n] = 0.f;
    for (int s = 0; s < SEG; s++) {
#pragma unroll
        for (int n = 0; n < NS; n++) {
            const size_t o = ((size_t)((b * SEG + s) * NS + n)) * DIN + d;
            g_hin[o] = h[n];
            h[n] = g_segA[o] * h[n] + g_segB[o];
        }
    }
}

// pass3: replay with correct h_in, compute y + D skip + silu(z) gating
__global__ __launch_bounds__(128) void scan_pass3(const float* __restrict__ A_log,
                                                  const float* __restrict__ D_skip) {
    const int b = blockIdx.z;
    const int s = blockIdx.y;
    const int d = blockIdx.x * 128 + threadIdx.x;
    const int tid = threadIdx.x;
    const int l0 = s * SEGL;

    float A[NS];
#pragma unroll
    for (int n = 0; n < NS; n++) A[n] = -__expf(A_log[d * NS + n]);
    const float dsk = D_skip[d];

    float h[NS];
#pragma unroll
    for (int n = 0; n < NS; n++)
        h[n] = g_hin[((size_t)((b * SEG + s) * NS + n)) * DIN + d];

    __shared__ float sB[SEGL][NS];
    __shared__ float sC[SEGL][NS];
    for (int i = tid; i < SEGL * NS * 2; i += 128) {
        const int ll = i >> 4;
        const int c = i & 15;
        const float v = g_dbl[((size_t)(b * LL + l0 + ll)) * DBLW + RR + c];
        if (c < NS) sB[ll][c] = v;
        else        sC[ll][c - NS] = v;
    }
    __syncthreads();

    for (int j = 0; j < SEGL; j++) {
        const size_t idx = ((size_t)(b * LL + l0 + j)) * DIN + d;
        const float dtv = g_dt[idx];
        const float xv = g_xconv[idx];
        const float dtx = dtv * xv;
        float yv = 0.f;
#pragma unroll
        for (int n = 0; n < NS; n++) {
            const float da = __expf(dtv * A[n]);
            h[n] = da * h[n] + dtx * sB[j][n];
            yv += h[n] * sC[j][n];
        }
        const float z = g_xz[((size_t)(b * LL + l0 + j)) * (2 * DIN) + DIN + d];
        const float sz = z / (1.f + __expf(-z));
        g_y[idx] = (yv + dsk * xv) * sz;
    }
}

// ---------------- launch ----------------
extern "C" void kernel_launch(void* const* d_in, const int* in_sizes, int n_in,
                              void* d_out, int out_size) {
    const float* hidden = (const float*)d_in[0];
    const float* norm_w = (const float*)d_in[1];
    const float* in_proj_w = (const float*)d_in[2];
    const float* conv_w = (const float*)d_in[3];
    const float* conv_b = (const float*)d_in[4];
    const float* x_proj_w = (const float*)d_in[5];
    const float* dt_proj_w = (const float*)d_in[6];
    const float* dt_proj_b = (const float*)d_in[7];
    const float* A_log = (const float*)d_in[8];
    const float* D_skip = (const float*)d_in[9];
    const float* out_proj_w = (const float*)d_in[10];
    float* out = (float*)d_out;

    float *p_xnorm, *p_xz, *p_xconv, *p_dbl, *p_dt, *p_y;
    cudaGetSymbolAddress((void**)&p_xnorm, g_xnorm);
    cudaGetSymbolAddress((void**)&p_xz, g_xz);
    cudaGetSymbolAddress((void**)&p_xconv, g_xconv);
    cudaGetSymbolAddress((void**)&p_dbl, g_dbl);
    cudaGetSymbolAddress((void**)&p_dt, g_dt);
    cudaGetSymbolAddress((void**)&p_y, g_y);

    const int M = BB * LL;  // 8192

    // 1. RMSNorm
    rmsnorm_kernel<<<M, 256>>>(hidden, norm_w);

    // 2. in_proj: xz[M, 2048] = xnorm[M,1024] @ in_proj_w^T
    {
        dim3 grid(2 * DIN / 128, M / 128);
        gemm_tf32<<<grid, 256>>>(p_xnorm, DD, in_proj_w, DD,
                                 p_xz, 2 * DIN, DD, 2 * DIN, nullptr, 0);
    }

    // 3. conv + silu
    {
        const int total = BB * LL * DIN;
        conv_silu_kernel<<<(total + 255) / 256, 256>>>(conv_w, conv_b);
    }

    // 4. x_proj: dbl[M, 80] = xconv[M,1024] @ x_proj_w^T
    {
        dim3 grid(1, M / 128);
        gemm_tf32<<<grid, 256>>>(p_xconv, DIN, x_proj_w, DIN,
                                 p_dbl, DBLW, DIN, DBLW, nullptr, 0);
    }

    // 5. dt_proj + bias + softplus: dt[M,1024] = softplus(dbl[:, :64] @ dt_proj_w^T + b)
    {
        dim3 grid(DIN / 128, M / 128);
        gemm_tf32<<<grid, 256>>>(p_dbl, DBLW, dt_proj_w, RR,
                                 p_dt, DIN, RR, DIN, dt_proj_b, 1);
    }

    // 6. chunked selective scan
    {
        dim3 grid1(DIN / 128, SEG, BB);
        scan_pass1<<<grid1, 128>>>(A_log);
        scan_pass2<<<(BB * DIN + 255) / 256, 256>>>();
        scan_pass3<<<grid1, 128>>>(A_log, D_skip);
    }

    // 7. out_proj: out[M,1024] = y[M,1024] @ out_proj_w^T
    {
        dim3 grid(DD / 128, M / 128);
        gemm_tf32<<<grid, 256>>>(p_y, DIN, out_proj_w, DIN,
                                 out, DD, DIN, DD, nullptr, 0);
    }
}

// round 3
// speedup vs baseline: 4.4455x; 1.3697x over previous
#include <cuda_runtime.h>
#include <math.h>
#include <stdint.h>

#define BB 4
#define LL 2048
#define DD 1024
#define DIN 1024
#define NS 8
#define RR 64
#define DBLW 80
#define SEG 16
#define SEGL 128
#define MTOT (BB*LL)
#define SPLITK 4

// ---------------- scratch ----------------
__device__ float g_xnorm[MTOT*DD];
__device__ float g_xz[MTOT*2*DIN];
__device__ float g_xconv[MTOT*DIN];
__device__ float g_dbl[MTOT*DBLW];
__device__ float g_dblp[SPLITK*MTOT*DBLW];
__device__ float g_dt[MTOT*DIN];
__device__ float g_y[MTOT*DIN];
__device__ float g_segA[BB*SEG*NS*DIN];
__device__ float g_segB[BB*SEG*NS*DIN];
__device__ float g_hin[BB*SEG*NS*DIN];
// tf32-rounded weights
__device__ float g_w_in[2*DIN*DD];
__device__ float g_w_x[DBLW*DIN];
__device__ float g_w_dt[DIN*RR];
__device__ float g_w_out[DD*DIN];

// ---------------- helpers ----------------
__device__ __forceinline__ float rnd_tf32(float f) {
    uint32_t u;
    asm("cvt.rna.tf32.f32 %0, %1;" : "=r"(u) : "f"(f));
    return __uint_as_float(u);
}

__device__ __forceinline__ void mma_tf32(float c[4], const uint32_t a[4], const uint32_t b[2]) {
    asm volatile(
        "mma.sync.aligned.m16n8k8.row.col.f32.tf32.tf32.f32 "
        "{%0,%1,%2,%3}, {%4,%5,%6,%7}, {%8,%9}, {%0,%1,%2,%3};"
        : "+f"(c[0]), "+f"(c[1]), "+f"(c[2]), "+f"(c[3])
        : "r"(a[0]), "r"(a[1]), "r"(a[2]), "r"(a[3]), "r"(b[0]), "r"(b[1]));
}

__device__ __forceinline__ void cp16(uint32_t dst, const void* src, bool v) {
    int sz = v ? 16 : 0;
    asm volatile("cp.async.cg.shared.global [%0], [%1], 16, %2;\n"
                 :: "r"(dst), "l"(src), "r"(sz));
}

// ---------------- weight convert (fp32 -> tf32-rounded bits) ----------------
#define NWI (2*DIN*DD)
#define NWX (DBLW*DIN)
#define NWDT (DIN*RR)
#define NWO (DD*DIN)
__global__ __launch_bounds__(256) void cvt_weights(const float* __restrict__ iw,
                                                   const float* __restrict__ xw,
                                                   const float* __restrict__ dw,
                                                   const float* __restrict__ ow) {
    int i = blockIdx.x * 256 + threadIdx.x;
    if (i < NWI) { g_w_in[i] = rnd_tf32(iw[i]); return; }
    i -= NWI;
    if (i < NWX) { g_w_x[i] = rnd_tf32(xw[i]); return; }
    i -= NWX;
    if (i < NWDT) { g_w_dt[i] = rnd_tf32(dw[i]); return; }
    i -= NWDT;
    if (i < NWO) { g_w_out[i] = rnd_tf32(ow[i]); }
}

// ---------------- RMSNorm (tf32-rounded output) ----------------
__global__ __launch_bounds__(256) void rmsnorm_kernel(const float* __restrict__ x,
                                                      const float* __restrict__ w) {
    const int row = blockIdx.x;
    const float* xr = x + (size_t)row * DD;
    float v[4];
    float ss = 0.f;
#pragma unroll
    for (int i = 0; i < 4; i++) {
        v[i] = xr[threadIdx.x + i * 256];
        ss += v[i] * v[i];
    }
#pragma unroll
    for (int o = 16; o > 0; o >>= 1) ss += __shfl_xor_sync(0xffffffffu, ss, o);
    __shared__ float red[8];
    if ((threadIdx.x & 31) == 0) red[threadIdx.x >> 5] = ss;
    __syncthreads();
    float tot = 0.f;
#pragma unroll
    for (int i = 0; i < 8; i++) tot += red[i];
    const float sc = rsqrtf(tot * (1.f / DD) + 1e-5f);
    float* outr = g_xnorm + (size_t)row * DD;
#pragma unroll
    for (int i = 0; i < 4; i++) {
        const int d = threadIdx.x + i * 256;
        outr[d] = rnd_tf32(v[i] * sc * w[d]);
    }
}

// ---------------- TF32 tensor-core GEMM, cp.async 4-stage ----------------
// C[m,e] = sum_k A[m, z*K + k] * W[e, z*K + k],  C += z*cstride
// A,W must be pre-rounded to tf32. BM=BN=128, BK=16, 256 thr, 8 warps.
// smem layout: [stage][row 0..127][k 0..15] stride 20 floats (conflict-free).
#define GSTAGES 4
#define GSTRIDE 20
#define STGF (128*GSTRIDE)            // floats per matrix-stage
#define STGB (STGF*4)                 // bytes per matrix-stage
#define GSMEM (2*GSTAGES*STGB)        // 81920 bytes

__global__ __launch_bounds__(256, 2) void gemm_tf32(
    const float* __restrict__ A, int lda,
    const float* __restrict__ W, int ldw,
    float* __restrict__ C, int ldc, size_t cstride,
    int K, int E,
    const float* __restrict__ bias, int epi)
{
    extern __shared__ float smem[];
    float* sA = smem;
    float* sB = smem + GSTAGES * STGF;

    const int tid = threadIdx.x;
    const int lane = tid & 31;
    const int wid = tid >> 5;
    const int m0 = blockIdx.y * 128;
    const int e0 = blockIdx.x * 128;
    const int z = blockIdx.z;
    const int mw = (wid & 3) * 32;
    const int nw = (wid >> 2) * 64;

    const int am = tid >> 2;          // 0..63 (+64)
    const int kq = (tid & 3) * 4;     // 0,4,8,12

    const size_t kof = (size_t)z * K + kq;
    const float* aP0 = A + (size_t)(m0 + am) * lda + kof;
    const float* aP1 = aP0 + (size_t)64 * lda;
    const int er0 = e0 + am, er1 = er0 + 64;
    const bool v0 = er0 < E, v1 = er1 < E;
    const float* wP0 = W + (size_t)(v0 ? er0 : 0) * ldw + kof;
    const float* wP1 = W + (size_t)(v1 ? er1 : 0) * ldw + kof;

    const uint32_t sAu = (uint32_t)__cvta_generic_to_shared(sA);
    const uint32_t sBu = (uint32_t)__cvta_generic_to_shared(sB);
    const uint32_t dA0 = sAu + (am * GSTRIDE + kq) * 4;
    const uint32_t dA1 = dA0 + 64 * GSTRIDE * 4;
    const uint32_t dB0 = sBu + (am * GSTRIDE + kq) * 4;
    const uint32_t dB1 = dB0 + 64 * GSTRIDE * 4;

    float acc[2][8][4];
#pragma unroll
    for (int i = 0; i < 2; i++)
#pragma unroll
        for (int j = 0; j < 8; j++)
#pragma unroll
            for (int l = 0; l < 4; l++) acc[i][j][l] = 0.f;

    const int T = K / 16;

    // prologue: stages 0..2
#pragma unroll
    for (int p = 0; p < GSTAGES - 1; p++) {
        const int ko = p * 16;
        const uint32_t so = p * STGB;
        cp16(dA0 + so, aP0 + ko, true);
        cp16(dA1 + so, aP1 + ko, true);
        cp16(dB0 + so, wP0 + ko, v0);
        cp16(dB1 + so, wP1 + ko, v1);
        asm volatile("cp.async.commit_group;\n");
    }

    const int g = lane >> 2;
    const int tg = lane & 3;

    for (int t = 0; t < T; t++) {
        asm volatile("cp.async.wait_group 2;\n");
        __syncthreads();

        const int stg = t & (GSTAGES - 1);
        const float* At = sA + stg * STGF;
        const float* Bt = sB + stg * STGF;

#pragma unroll
        for (int ks = 0; ks < 2; ks++) {
            const int kk = ks * 8;
            uint32_t af[2][4];
            uint32_t bf[8][2];
#pragma unroll
            for (int mt = 0; mt < 2; mt++) {
                const int mb = mw + mt * 16 + g;
                af[mt][0] = __float_as_uint(At[mb * GSTRIDE + kk + tg]);
                af[mt][1] = __float_as_uint(At[(mb + 8) * GSTRIDE + kk + tg]);
                af[mt][2] = __float_as_uint(At[mb * GSTRIDE + kk + 4 + tg]);
                af[mt][3] = __float_as_uint(At[(mb + 8) * GSTRIDE + kk + 4 + tg]);
            }
#pragma unroll
            for (int nt = 0; nt < 8; nt++) {
                const int nb = nw + nt * 8 + g;
                bf[nt][0] = __float_as_uint(Bt[nb * GSTRIDE + kk + tg]);
                bf[nt][1] = __float_as_uint(Bt[nb * GSTRIDE + kk + 4 + tg]);
            }
#pragma unroll
            for (int mt = 0; mt < 2; mt++)
#pragma unroll
                for (int nt = 0; nt < 8; nt++)
                    mma_tf32(acc[mt][nt], af[mt], bf[nt]);
        }

        // issue stage t+3
        if (t + GSTAGES - 1 < T) {
            const int tn = t + GSTAGES - 1;
            const int ko = tn * 16;
            const uint32_t so = (tn & (GSTAGES - 1)) * STGB;
            cp16(dA0 + so, aP0 + ko, true);
            cp16(dA1 + so, aP1 + ko, true);
            cp16(dB0 + so, wP0 + ko, v0);
            cp16(dB1 + so, wP1 + ko, v1);
        }
        asm volatile("cp.async.commit_group;\n");
    }

    // epilogue
    float* Cz = C + (size_t)z * cstride;
#pragma unroll
    for (int mt = 0; mt < 2; mt++) {
        const int r0 = m0 + mw + mt * 16 + g;
        const int r1 = r0 + 8;
#pragma unroll
        for (int nt = 0; nt < 8; nt++) {
            const int c0 = e0 + nw + nt * 8 + tg * 2;
#pragma unroll
            for (int jj = 0; jj < 2; jj++) {
                const int c = c0 + jj;
                if (c < E) {
                    float va = acc[mt][nt][jj];
                    float vb = acc[mt][nt][2 + jj];
                    if (epi == 1) {
                        const float bv = bias[c];
                        va += bv;
                        va = fmaxf(va, 0.f) + log1pf(__expf(-fabsf(va)));
                        vb += bv;
                        vb = fmaxf(vb, 0.f) + log1pf(__expf(-fabsf(vb)));
                    }
                    Cz[(size_t)r0 * ldc + c] = va;
                    Cz[(size_t)r1 * ldc + c] = vb;
                }
            }
        }
    }
}

// ---------------- split-K reduce for x_proj (tf32-rounded output) ----------------
__global__ __launch_bounds__(256) void reduce_dbl() {
    const int idx = blockIdx.x * 256 + threadIdx.x;
    if (idx >= MTOT * DBLW) return;
    float s = 0.f;
#pragma unroll
    for (int p = 0; p < SPLITK; p++) s += g_dblp[(size_t)p * MTOT * DBLW + idx];
    g_dbl[idx] = rnd_tf32(s);
}

// ---------------- causal depthwise conv (K=4) + bias + silu ----------------
__global__ __launch_bounds__(256) void conv_silu_kernel(const float* __restrict__ conv_w,
                                                        const float* __restrict__ conv_b) {
    const int idx = blockIdx.x * blockDim.x + threadIdx.x;
    if (idx >= BB * LL * DIN) return;
    const int d = idx % DIN;
    const int l = (idx / DIN) % LL;
    const int b = idx / (DIN * LL);
    const float* w = conv_w + d * 4;
    float acc = conv_b[d];
#pragma unroll
    for (int j = 0; j < 4; j++) {
        const int ls = l - 3 + j;
        if (ls >= 0) acc += w[j] * g_xz[((size_t)(b * LL + ls)) * (2 * DIN) + d];
    }
    const float s = acc / (1.f + __expf(-acc));
    g_xconv[idx] = rnd_tf32(s);   // feeds x_proj GEMM
}

// ---------------- chunked selective scan ----------------
__global__ __launch_bounds__(128) void scan_pass1(const float* __restrict__ A_log) {
    const int b = blockIdx.z;
    const int s = blockIdx.y;
    const int d = blockIdx.x * 128 + threadIdx.x;
    const int tid = threadIdx.x;
    const int l0 = s * SEGL;

    float A[NS];
#pragma unroll
    for (int n = 0; n < NS; n++) A[n] = -__expf(A_log[d * NS + n]);

    float p[NS], h[NS];
#pragma unroll
    for (int n = 0; n < NS; n++) { p[n] = 1.f; h[n] = 0.f; }

    __shared__ float sB[SEGL][NS];
    for (int i = tid; i < SEGL * NS; i += 128) {
        const int ll = i >> 3;
        const int n = i & 7;
        sB[ll][n] = g_dbl[((size_t)(b * LL + l0 + ll)) * DBLW + RR + n];
    }
    __syncthreads();

    for (int j = 0; j < SEGL; j++) {
        const size_t idx = ((size_t)(b * LL + l0 + j)) * DIN + d;
        const float dtv = g_dt[idx];
        const float xv = g_xconv[idx];
        const float dtx = dtv * xv;
#pragma unroll
        for (int n = 0; n < NS; n++) {
            const float da = __expf(dtv * A[n]);
            p[n] *= da;
            h[n] = da * h[n] + dtx * sB[j][n];
        }
    }
#pragma unroll
    for (int n = 0; n < NS; n++) {
        const size_t o = ((size_t)((b * SEG + s) * NS + n)) * DIN + d;
        g_segA[o] = p[n];
        g_segB[o] = h[n];
    }
}

__global__ __launch_bounds__(256) void scan_pass2() {
    const int gidx = blockIdx.x * 256 + threadIdx.x;
    if (gidx >= BB * DIN) return;
    const int b = gidx / DIN;
    const int d = gidx % DIN;
    float h[NS];
#pragma unroll
    for (int n = 0; n < NS; n++) h[n] = 0.f;
    for (int s = 0; s < SEG; s++) {
#pragma unroll
        for (int n = 0; n < NS; n++) {
            const size_t o = ((size_t)((b * SEG + s) * NS + n)) * DIN + d;
            g_hin[o] = h[n];
            h[n] = g_segA[o] * h[n] + g_segB[o];
        }
    }
}

__global__ __launch_bounds__(128) void scan_pass3(const float* __restrict__ A_log,
                                                  const float* __restrict__ D_skip) {
    const int b = blockIdx.z;
    const int s = blockIdx.y;
    const int d = blockIdx.x * 128 + threadIdx.x;
    const int tid = threadIdx.x;
    const int l0 = s * SEGL;

    float A[NS];
#pragma unroll
    for (int n = 0; n < NS; n++) A[n] = -__expf(A_log[d * NS + n]);
    const float dsk = D_skip[d];

    float h[NS];
#pragma unroll
    for (int n = 0; n < NS; n++)
        h[n] = g_hin[((size_t)((b * SEG + s) * NS + n)) * DIN + d];

    __shared__ float sB[SEGL][NS];
    __shared__ float sC[SEGL][NS];
    for (int i = tid; i < SEGL * NS * 2; i += 128) {
        const int ll = i >> 4;
        const int c = i & 15;
        const float v = g_dbl[((size_t)(b * LL + l0 + ll)) * DBLW + RR + c];
        if (c < NS) sB[ll][c] = v;
        else        sC[ll][c - NS] = v;
    }
    __syncthreads();

    for (int j = 0; j < SEGL; j++) {
        const size_t idx = ((size_t)(b * LL + l0 + j)) * DIN + d;
        const float dtv = g_dt[idx];
        const float xv = g_xconv[idx];
        const float dtx = dtv * xv;
        float yv = 0.f;
#pragma unroll
        for (int n = 0; n < NS; n++) {
            const float da = __expf(dtv * A[n]);
            h[n] = da * h[n] + dtx * sB[j][n];
            yv += h[n] * sC[j][n];
        }
        const float z = g_xz[((size_t)(b * LL + l0 + j)) * (2 * DIN) + DIN + d];
        const float sz = z / (1.f + __expf(-z));
        g_y[idx] = rnd_tf32((yv + dsk * xv) * sz);  // feeds out_proj GEMM
    }
}

// ---------------- launch ----------------
extern "C" void kernel_launch(void* const* d_in, const int* in_sizes, int n_in,
                              void* d_out, int out_size) {
    const float* hidden = (const float*)d_in[0];
    const float* norm_w = (const float*)d_in[1];
    const float* in_proj_w = (const float*)d_in[2];
    const float* conv_w = (const float*)d_in[3];
    const float* conv_b = (const float*)d_in[4];
    const float* x_proj_w = (const float*)d_in[5];
    const float* dt_proj_w = (const float*)d_in[6];
    const float* dt_proj_b = (const float*)d_in[7];
    const float* A_log = (const float*)d_in[8];
    const float* D_skip = (const float*)d_in[9];
    const float* out_proj_w = (const float*)d_in[10];
    float* out = (float*)d_out;

    float *p_xnorm, *p_xz, *p_xconv, *p_dbl, *p_dblp, *p_dt, *p_y;
    float *p_w_in, *p_w_x, *p_w_dt, *p_w_out;
    cudaGetSymbolAddress((void**)&p_xnorm, g_xnorm);
    cudaGetSymbolAddress((void**)&p_xz, g_xz);
    cudaGetSymbolAddress((void**)&p_xconv, g_xconv);
    cudaGetSymbolAddress((void**)&p_dbl, g_dbl);
    cudaGetSymbolAddress((void**)&p_dblp, g_dblp);
    cudaGetSymbolAddress((void**)&p_dt, g_dt);
    cudaGetSymbolAddress((void**)&p_y, g_y);
    cudaGetSymbolAddress((void**)&p_w_in, g_w_in);
    cudaGetSymbolAddress((void**)&p_w_x, g_w_x);
    cudaGetSymbolAddress((void**)&p_w_dt, g_w_dt);
    cudaGetSymbolAddress((void**)&p_w_out, g_w_out);

    cudaFuncSetAttribute(gemm_tf32, cudaFuncAttributeMaxDynamicSharedMemorySize, GSMEM);

    const int M = MTOT;  // 8192

    // 0. convert weights to tf32-rounded
    {
        const int total = NWI + NWX + NWDT + NWO;
        cvt_weights<<<(total + 255) / 256, 256>>>(in_proj_w, x_proj_w, dt_proj_w, out_proj_w);
    }

    // 1. RMSNorm (rounded)
    rmsnorm_kernel<<<M, 256>>>(hidden, norm_w);

    // 2. in_proj: xz[M,2048] = xnorm @ w_in^T
    {
        dim3 grid(2 * DIN / 128, M / 128, 1);
        gemm_tf32<<<grid, 256, GSMEM>>>(p_xnorm, DD, p_w_in, DD,
                                        p_xz, 2 * DIN, 0, DD, 2 * DIN, nullptr, 0);
    }

    // 3. conv + silu (rounded)
    {
        const int total = BB * LL * DIN;
        conv_silu_kernel<<<(total + 255) / 256, 256>>>(conv_w, conv_b);
    }

    // 4. x_proj split-K: dblp[z][M,80] = xconv[:, z*256:(z+1)*256] @ w_x^T
    {
        dim3 grid(1, M / 128, SPLITK);
        gemm_tf32<<<grid, 256, GSMEM>>>(p_xconv, DIN, p_w_x, DIN,
                                        p_dblp, DBLW, (size_t)MTOT * DBLW,
                                        DIN / SPLITK, DBLW, nullptr, 0);
        reduce_dbl<<<(MTOT * DBLW + 255) / 256, 256>>>();
    }

    // 5. dt_proj + bias + softplus
    {
        dim3 grid(DIN / 128, M / 128, 1);
        gemm_tf32<<<grid, 256, GSMEM>>>(p_dbl, DBLW, p_w_dt, RR,
                                        p_dt, DIN, 0, RR, DIN, dt_proj_b, 1);
    }

    // 6. chunked selective scan
    {
        dim3 grid1(DIN / 128, SEG, BB);
        scan_pass1<<<grid1, 128>>>(A_log);
        scan_pass2<<<(BB * DIN + 255) / 256, 256>>>();
        scan_pass3<<<grid1, 128>>>(A_log, D_skip);
    }

    // 7. out_proj
    {
        dim3 grid(DD / 128, M / 128, 1);
        gemm_tf32<<<grid, 256, GSMEM>>>(p_y, DIN, p_w_out, DIN,
                                        out, DD, 0, DIN, DD, nullptr, 0);
    }
}

// round 4
// speedup vs baseline: 4.8655x; 1.0945x over previous
#include <cuda_runtime.h>
#include <math.h>
#include <stdint.h>

#define BB 4
#define LL 2048
#define DD 1024
#define DIN 1024
#define NS 8
#define RR 64
#define DBLW 80
#define SEG 16
#define SEGL 128
#define MTOT (BB*LL)
#define SPLITK 4

// ---------------- scratch ----------------
__device__ float g_xnorm[MTOT*DD];
__device__ float g_xz[MTOT*2*DIN];
__device__ float g_xconv[MTOT*DIN];
__device__ float g_dbl[MTOT*DBLW];
__device__ float g_dblp[SPLITK*MTOT*DBLW];
__device__ float g_dt[MTOT*DIN];
__device__ float g_y[MTOT*DIN];
__device__ float g_segA[BB*SEG*NS*DIN];
__device__ float g_segB[BB*SEG*NS*DIN];
__device__ float g_hin[BB*SEG*NS*DIN];
__device__ float g_w_in[2*DIN*DD];
__device__ float g_w_x[DBLW*DIN];
__device__ float g_w_dt[DIN*RR];
__device__ float g_w_out[DD*DIN];

// ---------------- helpers ----------------
__device__ __forceinline__ float rnd_tf32(float f) {
    uint32_t u;
    asm("cvt.rna.tf32.f32 %0, %1;" : "=r"(u) : "f"(f));
    return __uint_as_float(u);
}

__device__ __forceinline__ void mma_tf32(float c[4], const uint32_t a[4], const uint32_t b[2]) {
    asm volatile(
        "mma.sync.aligned.m16n8k8.row.col.f32.tf32.tf32.f32 "
        "{%0,%1,%2,%3}, {%4,%5,%6,%7}, {%8,%9}, {%0,%1,%2,%3};"
        : "+f"(c[0]), "+f"(c[1]), "+f"(c[2]), "+f"(c[3])
        : "r"(a[0]), "r"(a[1]), "r"(a[2]), "r"(a[3]), "r"(b[0]), "r"(b[1]));
}

__device__ __forceinline__ void cp16(uint32_t dst, const void* src, bool v) {
    int sz = v ? 16 : 0;
    asm volatile("cp.async.cg.shared.global [%0], [%1], 16, %2;\n"
                 :: "r"(dst), "l"(src), "r"(sz));
}

// ---------------- weight convert (vectorized) ----------------
#define NWI (2*DIN*DD)
#define NWX (DBLW*DIN)
#define NWDT (DIN*RR)
#define NWO (DD*DIN)
__global__ __launch_bounds__(256) void cvt_weights(const float4* __restrict__ iw,
                                                   const float4* __restrict__ xw,
                                                   const float4* __restrict__ dw,
                                                   const float4* __restrict__ ow) {
    int i = blockIdx.x * 256 + threadIdx.x;
    const float4* src;
    float4* dst;
    if (i < NWI/4) { src = iw + i; dst = (float4*)g_w_in + i; }
    else if ((i -= NWI/4) < NWX/4) { src = xw + i; dst = (float4*)g_w_x + i; }
    else if ((i -= NWX/4) < NWDT/4) { src = dw + i; dst = (float4*)g_w_dt + i; }
    else if ((i -= NWDT/4) < NWO/4) { src = ow + i; dst = (float4*)g_w_out + i; }
    else return;
    float4 v = *src;
    v.x = rnd_tf32(v.x); v.y = rnd_tf32(v.y);
    v.z = rnd_tf32(v.z); v.w = rnd_tf32(v.w);
    *dst = v;
}

// ---------------- RMSNorm (float4, tf32-rounded output) ----------------
__global__ __launch_bounds__(256) void rmsnorm_kernel(const float* __restrict__ x,
                                                      const float* __restrict__ w) {
    const int row = blockIdx.x;
    const float4 v = *((const float4*)(x + (size_t)row * DD) + threadIdx.x);
    float ss = v.x*v.x + v.y*v.y + v.z*v.z + v.w*v.w;
#pragma unroll
    for (int o = 16; o > 0; o >>= 1) ss += __shfl_xor_sync(0xffffffffu, ss, o);
    __shared__ float red[8];
    if ((threadIdx.x & 31) == 0) red[threadIdx.x >> 5] = ss;
    __syncthreads();
    float tot = 0.f;
#pragma unroll
    for (int i = 0; i < 8; i++) tot += red[i];
    const float sc = rsqrtf(tot * (1.f / DD) + 1e-5f);
    const float4 wv = *((const float4*)w + threadIdx.x);
    float4 o;
    o.x = rnd_tf32(v.x * sc * wv.x);
    o.y = rnd_tf32(v.y * sc * wv.y);
    o.z = rnd_tf32(v.z * sc * wv.z);
    o.w = rnd_tf32(v.w * sc * wv.w);
    *((float4*)(g_xnorm + (size_t)row * DD) + threadIdx.x) = o;
}

// ---------------- TF32 tensor-core GEMM, BK=32, 3-stage cp.async ----------------
#define GSTAGES 3
#define GSTRIDE 36
#define STGF (128*GSTRIDE)
#define STGB (STGF*4)
#define GSMEM (2*GSTAGES*STGB)    // 110592 bytes

__global__ __launch_bounds__(256, 2) void gemm_tf32(
    const float* __restrict__ A, int lda,
    const float* __restrict__ W, int ldw,
    float* __restrict__ C, int ldc, size_t cstride,
    int K, int E,
    const float* __restrict__ bias, int epi)
{
    extern __shared__ float smem[];
    float* sA = smem;
    float* sB = smem + GSTAGES * STGF;

    const int tid = threadIdx.x;
    const int lane = tid & 31;
    const int wid = tid >> 5;
    const int m0 = blockIdx.y * 128;
    const int e0 = blockIdx.x * 128;
    const int z = blockIdx.z;
    const int mw = (wid & 3) * 32;
    const int nw = (wid >> 2) * 64;

    // producer mapping: 32 rows x 8 k-quads; 4 row-chunks
    const int prow = tid >> 3;        // 0..31
    const int pk = (tid & 7) * 4;     // 0..28

    const float* aP[4];
    const float* wP[4];
    bool wv[4];
    uint32_t dAo[4], dBo[4];
    const uint32_t sAu = (uint32_t)__cvta_generic_to_shared(sA);
    const uint32_t sBu = (uint32_t)__cvta_generic_to_shared(sB);
#pragma unroll
    for (int c = 0; c < 4; c++) {
        const int r = prow + 32 * c;
        aP[c] = A + (size_t)(m0 + r) * lda + (size_t)z * K + pk;
        const int er = e0 + r;
        wv[c] = er < E;
        wP[c] = W + (size_t)(wv[c] ? er : 0) * ldw + (size_t)z * K + pk;
        dAo[c] = sAu + (r * GSTRIDE + pk) * 4;
        dBo[c] = sBu + (r * GSTRIDE + pk) * 4;
    }

    float acc[2][8][4];
#pragma unroll
    for (int i = 0; i < 2; i++)
#pragma unroll
        for (int j = 0; j < 8; j++)
#pragma unroll
            for (int l = 0; l < 4; l++) acc[i][j][l] = 0.f;

    const int T = K / 32;

    // prologue: stages 0,1
#pragma unroll
    for (int p = 0; p < GSTAGES - 1; p++) {
        const int ko = p * 32;
        const uint32_t so = p * STGB;
#pragma unroll
        for (int c = 0; c < 4; c++) {
            cp16(dAo[c] + so, aP[c] + ko, true);
            cp16(dBo[c] + so, wP[c] + ko, wv[c]);
        }
        asm volatile("cp.async.commit_group;\n");
    }

    const int g = lane >> 2;
    const int tg = lane & 3;

    for (int t = 0; t < T; t++) {
        asm volatile("cp.async.wait_group 1;\n");
        __syncthreads();

        const int stg = t % GSTAGES;
        const float* At = sA + stg * STGF;
        const float* Bt = sB + stg * STGF;

#pragma unroll
        for (int ks = 0; ks < 4; ks++) {
            const int kk = ks * 8;
            uint32_t af[2][4];
            uint32_t bf[8][2];
#pragma unroll
            for (int mt = 0; mt < 2; mt++) {
                const int mb = mw + mt * 16 + g;
                af[mt][0] = __float_as_uint(At[mb * GSTRIDE + kk + tg]);
                af[mt][1] = __float_as_uint(At[(mb + 8) * GSTRIDE + kk + tg]);
                af[mt][2] = __float_as_uint(At[mb * GSTRIDE + kk + 4 + tg]);
                af[mt][3] = __float_as_uint(At[(mb + 8) * GSTRIDE + kk + 4 + tg]);
            }
#pragma unroll
            for (int nt = 0; nt < 8; nt++) {
                const int nb = nw + nt * 8 + g;
                bf[nt][0] = __float_as_uint(Bt[nb * GSTRIDE + kk + tg]);
                bf[nt][1] = __float_as_uint(Bt[nb * GSTRIDE + kk + 4 + tg]);
            }
#pragma unroll
            for (int mt = 0; mt < 2; mt++)
#pragma unroll
                for (int nt = 0; nt < 8; nt++)
                    mma_tf32(acc[mt][nt], af[mt], bf[nt]);
        }

        if (t + GSTAGES - 1 < T) {
            const int tn = t + GSTAGES - 1;
            const int ko = tn * 32;
            const uint32_t so = (tn % GSTAGES) * STGB;
#pragma unroll
            for (int c = 0; c < 4; c++) {
                cp16(dAo[c] + so, aP[c] + ko, true);
                cp16(dBo[c] + so, wP[c] + ko, wv[c]);
            }
        }
        asm volatile("cp.async.commit_group;\n");
    }

    // epilogue
    float* Cz = C + (size_t)z * cstride;
#pragma unroll
    for (int mt = 0; mt < 2; mt++) {
        const int r0 = m0 + mw + mt * 16 + g;
        const int r1 = r0 + 8;
#pragma unroll
        for (int nt = 0; nt < 8; nt++) {
            const int c0 = e0 + nw + nt * 8 + tg * 2;
#pragma unroll
            for (int jj = 0; jj < 2; jj++) {
                const int c = c0 + jj;
                if (c < E) {
                    float va = acc[mt][nt][jj];
                    float vb = acc[mt][nt][2 + jj];
                    if (epi == 1) {
                        const float bv = bias[c];
                        va += bv;
                        va = fmaxf(va, 0.f) + log1pf(__expf(-fabsf(va)));
                        vb += bv;
                        vb = fmaxf(vb, 0.f) + log1pf(__expf(-fabsf(vb)));
                    }
                    Cz[(size_t)r0 * ldc + c] = va;
                    Cz[(size_t)r1 * ldc + c] = vb;
                }
            }
        }
    }
}

// ---------------- split-K reduce for x_proj ----------------
__global__ __launch_bounds__(256) void reduce_dbl() {
    const int idx = blockIdx.x * 256 + threadIdx.x;
    if (idx >= MTOT * DBLW) return;
    float s = 0.f;
#pragma unroll
    for (int p = 0; p < SPLITK; p++) s += g_dblp[(size_t)p * MTOT * DBLW + idx];
    g_dbl[idx] = rnd_tf32(s);
}

// ---------------- conv+silu: 4l x 4d per thread, all float4 ----------------
__global__ __launch_bounds__(256) void conv_silu_kernel(const float* __restrict__ conv_w,
                                                        const float* __restrict__ conv_b) {
    const int t = blockIdx.x * 256 + threadIdx.x;
    const int nd4 = DIN / 4;                 // 256
    const int d0 = (t % nd4) * 4;
    const int m0 = (t / nd4) * 4;            // 4 consecutive rows, same batch (LL%4==0)
    if (m0 >= MTOT) return;
    const int l0 = m0 % LL;
    const int b = m0 / LL;

    float4 xr[7];
#pragma unroll
    for (int j = 0; j < 7; j++) {
        const int ls = l0 - 3 + j;
        if (ls >= 0)
            xr[j] = *(const float4*)(g_xz + ((size_t)(b * LL + ls)) * (2 * DIN) + d0);
        else
            xr[j] = make_float4(0.f, 0.f, 0.f, 0.f);
    }
    float4 w0 = *(const float4*)(conv_w + (d0 + 0) * 4);
    float4 w1 = *(const float4*)(conv_w + (d0 + 1) * 4);
    float4 w2 = *(const float4*)(conv_w + (d0 + 2) * 4);
    float4 w3 = *(const float4*)(conv_w + (d0 + 3) * 4);
    const float4 bv = *(const float4*)(conv_b + d0);

#pragma unroll
    for (int i = 0; i < 4; i++) {
        float4 acc;
        acc.x = bv.x + w0.x * xr[i].x + w0.y * xr[i+1].x + w0.z * xr[i+2].x + w0.w * xr[i+3].x;
        acc.y = bv.y + w1.x * xr[i].y + w1.y * xr[i+1].y + w1.z * xr[i+2].y + w1.w * xr[i+3].y;
        acc.z = bv.z + w2.x * xr[i].z + w2.y * xr[i+1].z + w2.z * xr[i+2].z + w2.w * xr[i+3].z;
        acc.w = bv.w + w3.x * xr[i].w + w3.y * xr[i+1].w + w3.z * xr[i+2].w + w3.w * xr[i+3].w;
        float4 o;
        o.x = rnd_tf32(acc.x / (1.f + __expf(-acc.x)));
        o.y = rnd_tf32(acc.y / (1.f + __expf(-acc.y)));
        o.z = rnd_tf32(acc.z / (1.f + __expf(-acc.z)));
        o.w = rnd_tf32(acc.w / (1.f + __expf(-acc.w)));
        *(float4*)(g_xconv + ((size_t)(m0 + i)) * DIN + d0) = o;
    }
}

// ---------------- chunked selective scan ----------------
__global__ __launch_bounds__(128) void scan_pass1(const float* __restrict__ A_log) {
    const int b = blockIdx.z;
    const int s = blockIdx.y;
    const int d = blockIdx.x * 128 + threadIdx.x;
    const int tid = threadIdx.x;
    const int l0 = s * SEGL;

    float A[NS];
#pragma unroll
    for (int n = 0; n < NS; n++) A[n] = -__expf(A_log[d * NS + n]);

    float p[NS], h[NS];
#pragma unroll
    for (int n = 0; n < NS; n++) { p[n] = 1.f; h[n] = 0.f; }

    __shared__ float sB[SEGL][NS];
    for (int i = tid; i < SEGL * NS; i += 128) {
        const int ll = i >> 3;
        const int n = i & 7;
        sB[ll][n] = g_dbl[((size_t)(b * LL + l0 + ll)) * DBLW + RR + n];
    }
    __syncthreads();

    for (int j = 0; j < SEGL; j++) {
        const size_t idx = ((size_t)(b * LL + l0 + j)) * DIN + d;
        const float dtv = g_dt[idx];
        const float xv = g_xconv[idx];
        const float dtx = dtv * xv;
#pragma unroll
        for (int n = 0; n < NS; n++) {
            const float da = __expf(dtv * A[n]);
            p[n] *= da;
            h[n] = da * h[n] + dtx * sB[j][n];
        }
    }
#pragma unroll
    for (int n = 0; n < NS; n++) {
        const size_t o = ((size_t)((b * SEG + s) * NS + n)) * DIN + d;
        g_segA[o] = p[n];
        g_segB[o] = h[n];
    }
}

__global__ __launch_bounds__(256) void scan_pass2() {
    const int gidx = blockIdx.x * 256 + threadIdx.x;
    if (gidx >= BB * DIN) return;
    const int b = gidx / DIN;
    const int d = gidx % DIN;
    float h[NS];
#pragma unroll
    for (int n = 0; n < NS; n++) h[n] = 0.f;
    for (int s = 0; s < SEG; s++) {
#pragma unroll
        for (int n = 0; n < NS; n++) {
            const size_t o = ((size_t)((b * SEG + s) * NS + n)) * DIN + d;
            g_hin[o] = h[n];
            h[n] = g_segA[o] * h[n] + g_segB[o];
        }
    }
}

__global__ __launch_bounds__(128) void scan_pass3(const float* __restrict__ A_log,
                                                  const float* __restrict__ D_skip) {
    const int b = blockIdx.z;
    const int s = blockIdx.y;
    const int d = blockIdx.x * 128 + threadIdx.x;
    const int tid = threadIdx.x;
    const int l0 = s * SEGL;

    float A[NS];
#pragma unroll
    for (int n = 0; n < NS; n++) A[n] = -__expf(A_log[d * NS + n]);
    const float dsk = D_skip[d];

    float h[NS];
#pragma unroll
    for (int n = 0; n < NS; n++)
        h[n] = g_hin[((size_t)((b * SEG + s) * NS + n)) * DIN + d];

    __shared__ float sB[SEGL][NS];
    __shared__ float sC[SEGL][NS];
    for (int i = tid; i < SEGL * NS * 2; i += 128) {
        const int ll = i >> 4;
        const int c = i & 15;
        const float v = g_dbl[((size_t)(b * LL + l0 + ll)) * DBLW + RR + c];
        if (c < NS) sB[ll][c] = v;
        else        sC[ll][c - NS] = v;
    }
    __syncthreads();

    for (int j = 0; j < SEGL; j++) {
        const size_t idx = ((size_t)(b * LL + l0 + j)) * DIN + d;
        const float dtv = g_dt[idx];
        const float xv = g_xconv[idx];
        const float dtx = dtv * xv;
        float yv = 0.f;
#pragma unroll
        for (int n = 0; n < NS; n++) {
            const float da = __expf(dtv * A[n]);
            h[n] = da * h[n] + dtx * sB[j][n];
            yv += h[n] * sC[j][n];
        }
        const float z = g_xz[((size_t)(b * LL + l0 + j)) * (2 * DIN) + DIN + d];
        const float sz = z / (1.f + __expf(-z));
        g_y[idx] = rnd_tf32((yv + dsk * xv) * sz);
    }
}

// ---------------- launch ----------------
extern "C" void kernel_launch(void* const* d_in, const int* in_sizes, int n_in,
                              void* d_out, int out_size) {
    const float* hidden = (const float*)d_in[0];
    const float* norm_w = (const float*)d_in[1];
    const float* in_proj_w = (const float*)d_in[2];
    const float* conv_w = (const float*)d_in[3];
    const float* conv_b = (const float*)d_in[4];
    const float* x_proj_w = (const float*)d_in[5];
    const float* dt_proj_w = (const float*)d_in[6];
    const float* dt_proj_b = (const float*)d_in[7];
    const float* A_log = (const float*)d_in[8];
    const float* D_skip = (const float*)d_in[9];
    const float* out_proj_w = (const float*)d_in[10];
    float* out = (float*)d_out;

    float *p_xnorm, *p_xz, *p_xconv, *p_dbl, *p_dblp, *p_dt, *p_y;
    float *p_w_in, *p_w_x, *p_w_dt, *p_w_out;
    cudaGetSymbolAddress((void**)&p_xnorm, g_xnorm);
    cudaGetSymbolAddress((void**)&p_xz, g_xz);
    cudaGetSymbolAddress((void**)&p_xconv, g_xconv);
    cudaGetSymbolAddress((void**)&p_dbl, g_dbl);
    cudaGetSymbolAddress((void**)&p_dblp, g_dblp);
    cudaGetSymbolAddress((void**)&p_dt, g_dt);
    cudaGetSymbolAddress((void**)&p_y, g_y);
    cudaGetSymbolAddress((void**)&p_w_in, g_w_in);
    cudaGetSymbolAddress((void**)&p_w_x, g_w_x);
    cudaGetSymbolAddress((void**)&p_w_dt, g_w_dt);
    cudaGetSymbolAddress((void**)&p_w_out, g_w_out);

    cudaFuncSetAttribute(gemm_tf32, cudaFuncAttributeMaxDynamicSharedMemorySize, GSMEM);

    const int M = MTOT;

    // 0. weights -> tf32
    {
        const int total4 = (NWI + NWX + NWDT + NWO) / 4;
        cvt_weights<<<(total4 + 255) / 256, 256>>>((const float4*)in_proj_w,
                                                   (const float4*)x_proj_w,
                                                   (const float4*)dt_proj_w,
                                                   (const float4*)out_proj_w);
    }

    // 1. RMSNorm
    rmsnorm_kernel<<<M, 256>>>(hidden, norm_w);

    // 2. in_proj
    {
        dim3 grid(2 * DIN / 128, M / 128, 1);
        gemm_tf32<<<grid, 256, GSMEM>>>(p_xnorm, DD, p_w_in, DD,
                                        p_xz, 2 * DIN, 0, DD, 2 * DIN, nullptr, 0);
    }

    // 3. conv + silu
    {
        const int total = (MTOT / 4) * (DIN / 4);
        conv_silu_kernel<<<(total + 255) / 256, 256>>>(conv_w, conv_b);
    }

    // 4. x_proj split-K
    {
        dim3 grid(1, M / 128, SPLITK);
        gemm_tf32<<<grid, 256, GSMEM>>>(p_xconv, DIN, p_w_x, DIN,
                                        p_dblp, DBLW, (size_t)MTOT * DBLW,
                                        DIN / SPLITK, DBLW, nullptr, 0);
        reduce_dbl<<<(MTOT * DBLW + 255) / 256, 256>>>();
    }

    // 5. dt_proj + bias + softplus
    {
        dim3 grid(DIN / 128, M / 128, 1);
        gemm_tf32<<<grid, 256, GSMEM>>>(p_dbl, DBLW, p_w_dt, RR,
                                        p_dt, DIN, 0, RR, DIN, dt_proj_b, 1);
    }

    // 6. selective scan
    {
        dim3 grid1(DIN / 128, SEG, BB);
        scan_pass1<<<grid1, 128>>>(A_log);
        scan_pass2<<<(BB * DIN + 255) / 256, 256>>>();
        scan_pass3<<<grid1, 128>>>(A_log, D_skip);
    }

    // 7. out_proj
    {
        dim3 grid(DD / 128, M / 128, 1);
        gemm_tf32<<<grid, 256, GSMEM>>>(p_y, DIN, p_w_out, DIN,
                                        out, DD, 0, DIN, DD, nullptr, 0);
    }
}